// round 7
// baseline (speedup 1.0000x reference)
#include <cuda_runtime.h>
#include <cuda_bf16.h>
#include <cstdint>

// Problem constants (shapes fixed by dataset)
#define BB   16      // batch
#define CC   32      // channels in added; original has CC+1
#define HH   256     // grid H = W
#define TT   20      // boxes per batch
#define CELLS (HH*HH)
#define VOX  0.8f
#define INVVOX 1.25f

#define BLK   128    // threads per block (4 warps)
#define GRP   32     // cell-groups (of 4 cells) per block
#define GX    (CELLS / 4 / GRP)     // 512 blocks along cell dim
#define NBLOCKS (GX * BB)           // 8192

#define LDG4(dst, p)                                                     \
    asm volatile("ld.global.nc.v4.u32 {%0,%1,%2,%3}, [%4];"              \
                 : "=r"((dst).x), "=r"((dst).y), "=r"((dst).z), "=r"((dst).w) \
                 : "l"(p))

// Cross-block scratch (no cudaMalloc allowed). Zero-initialized at load;
// the last block resets everything so every graph replay starts clean.
__device__ unsigned int g_inter[BB];
__device__ unsigned int g_union[BB];
__device__ unsigned int g_ticket;

__global__ void __launch_bounds__(BLK)
k_fused(const float* __restrict__ added,
        const float* __restrict__ orig,
        const float* __restrict__ boxes,
        float* __restrict__ out) {
    const int b    = blockIdx.y;
    const int tid  = threadIdx.x;
    const int lane = tid & 31;
    const int w    = tid >> 5;          // warp id 0..3 = channel-set id

    // ---- shared state ------------------------------------------------------
    __shared__ float s_cx[TT], s_cy[TT], s_c[TT], s_s[TT], s_hx[TT], s_hy[TT];
    __shared__ int   s_i0[TT], s_i1[TT], s_j0[TT], s_j1[TT];
    __shared__ unsigned int s_mword[GRP];          // 4 mask bits per group
    __shared__ uint4 s_accA[2][GRP];               // partial ORs: added
    __shared__ uint4 s_accO[2][GRP];               // partial ORs: orig

    if (tid < TT) {
        const float* bx = boxes + ((size_t)b * TT + tid) * 7;
        const float cx = bx[0], cy = bx[1], cz = bx[2];
        const float dx = bx[3], dy = bx[4], dz = bx[5], yaw = bx[6];
        const float c  = cosf(yaw), s = sinf(yaw);
        const float hx = 0.5f * dx, hy = 0.5f * dy;
        const float ax = hx * fabsf(c) + hy * fabsf(s);   // rotated AABB
        const float ay = hx * fabsf(s) + hy * fabsf(c);
        int i0 = max(0,      (int)floorf((cx - ax) * INVVOX) - 1);
        int i1 = min(HH - 1, (int)ceilf ((cx + ax) * INVVOX) + 1);
        int j0 = max(0,      (int)floorf((cy - ay) * INVVOX) - 1);
        int j1 = min(HH - 1, (int)ceilf ((cy + ay) * INVVOX) + 1);
        // z test constant per box: |0.8 - cz| <= dz/2  (reference uses <=)
        if (fabsf(VOX - cz) > 0.5f * dz) { i0 = 1; i1 = 0; }  // empty AABB
        s_cx[tid] = cx;  s_cy[tid] = cy;
        s_c [tid] = c;   s_s [tid] = s;
        s_hx[tid] = hx;  s_hy[tid] = hy;
        s_i0[tid] = i0;  s_i1[tid] = i1;
        s_j0[tid] = j0;  s_j1[tid] = j1;
    }
    __syncthreads();

    // ---- phase 1: box test, one group (4 cells) per thread, threads 0..31 --
    const int grp0 = blockIdx.x * GRP;             // first group of this block
    if (tid < GRP) {
        const int cell0 = (grp0 + tid) * 4;
        const int i     = cell0 >> 8;              // row
        const int jbase = cell0 & 255;             // first column
        const float px  = (float)i * VOX;
        unsigned int mword = 0u;
        for (int t = 0; t < TT; t++) {
            if (i < s_i0[t] || i > s_i1[t]) continue;
            if (jbase + 3 < s_j0[t] || jbase > s_j1[t]) continue;
            const float c  = s_c[t],  s  = s_s[t];
            const float hx = s_hx[t], hy = s_hy[t];
            const float dxp = px - s_cx[t];
            const float cy  = s_cy[t];
            #pragma unroll
            for (int k = 0; k < 4; k++) {
                const float py = (float)(jbase + k) * VOX - cy;
                const float rx = fmaf(py, s,  dxp * c);
                const float ry = fmaf(py, c, -dxp * s);
                if (fabsf(rx) < hx && fabsf(ry) < hy) mword |= (1u << k);
            }
            if (mword == 0xFu) break;
        }
        s_mword[tid] = mword;
    }
    __syncthreads();

    // ---- phase 2: channel-split masked OR reduce ---------------------------
    // warp 0: added ch  0..15   warp 1: added ch 16..31
    // warp 2: orig  ch  1..16   warp 3: orig  ch 17..32
    // lane = group; each load instr covers 32 consecutive uint4 (512B).
    const unsigned int mw = s_mword[lane];
    uint4 acc = make_uint4(0u, 0u, 0u, 0u);
    if (mw != 0u) {
        const int grp = grp0 + lane;               // uint4 index in a plane
        const uint4* base;
        if (w < 2)
            base = (const uint4*)added + ((size_t)b * CC + w * 16)          * (CELLS/4) + grp;
        else
            base = (const uint4*)orig  + ((size_t)b * (CC+1) + 1 + (w-2)*16) * (CELLS/4) + grp;
        uint4 v[16];
        #pragma unroll
        for (int u = 0; u < 16; u++)
            LDG4(v[u], base + (size_t)u * (CELLS/4));
        #pragma unroll
        for (int u = 0; u < 16; u++) {
            acc.x |= v[u].x; acc.y |= v[u].y; acc.z |= v[u].z; acc.w |= v[u].w;
        }
    }
    if (w < 2) s_accA[w][lane]     = acc;
    else       s_accO[w - 2][lane] = acc;
    __syncthreads();

    // ---- phase 3: combine + count (warp 0 only) ----------------------------
    unsigned int vi = 0u, vu = 0u;
    if (w == 0) {
        const uint4 a0 = s_accA[0][lane], a1 = s_accA[1][lane];
        const uint4 o0 = s_accO[0][lane], o1 = s_accO[1][lane];
        const unsigned int av[4] = {a0.x | a1.x, a0.y | a1.y, a0.z | a1.z, a0.w | a1.w};
        const unsigned int ov[4] = {o0.x | o1.x, o0.y | o1.y, o0.z | o1.z, o0.w | o1.w};
        unsigned int inter = 0u, uni = 0u;
        #pragma unroll
        for (int k = 0; k < 4; k++) {
            const bool m = (mw >> k) & 1u;
            const bool p = m && (av[k] != 0u);
            const bool o = m && (ov[k] != 0u);
            inter += (unsigned)(p && o);
            uni   += (unsigned)(p || o);
        }
        vi = __reduce_add_sync(0xFFFFFFFFu, inter);
        vu = __reduce_add_sync(0xFFFFFFFFu, uni);
        if (lane == 0 && (vi | vu)) {
            atomicAdd(&g_inter[b], vi);
            atomicAdd(&g_union[b], vu);
        }
    }

    // ---- last-block finalization (+ scratch reset for graph replay) -------
    __shared__ unsigned int s_last;
    if (tid == 0) {
        __threadfence();
        s_last = (atomicAdd(&g_ticket, 1u) == (unsigned)(NBLOCKS - 1)) ? 1u : 0u;
    }
    __syncthreads();
    if (s_last && w == 0) {
        float iou = 0.0f;
        if (lane < BB) {
            const unsigned int ai = g_inter[lane];
            const unsigned int au = g_union[lane];
            g_inter[lane] = 0u;                  // reset for next replay
            g_union[lane] = 0u;
            iou = (float)ai / fmaxf((float)au, 1.0f);
        }
        #pragma unroll
        for (int off = 16; off > 0; off >>= 1)
            iou += __shfl_xor_sync(0xFFFFFFFFu, iou, off);
        if (lane == 0) {
            out[0] = (float)TT * iou / (float)BB;
            __threadfence();
            g_ticket = 0u;                       // reset ticket for next replay
        }
    }
}

extern "C" void kernel_launch(void* const* d_in, const int* in_sizes, int n_in,
                              void* d_out, int out_size) {
    const float* added = (const float*)d_in[0];   // (16,32,256,256)
    const float* orig  = (const float*)d_in[1];   // (16,33,256,256)
    const float* boxes = (const float*)d_in[2];   // (16,20,7)
    (void)in_sizes; (void)n_in; (void)out_size;   // tf_ego unused

    k_fused<<<dim3(GX, BB), BLK>>>(added, orig, boxes, (float*)d_out);
}

// round 8
// speedup vs baseline: 1.3243x; 1.3243x over previous
#include <cuda_runtime.h>
#include <cuda_bf16.h>
#include <cstdint>

// Problem constants (shapes fixed by dataset)
#define BB   16      // batch
#define CC   32      // channels in added; original has CC+1
#define HH   256     // grid H = W
#define TT   20      // boxes per batch
#define CELLS (HH*HH)
#define VOX  0.8f
#define INVVOX 1.25f

#define GX_IOU   64
#define NBLOCKS  (GX_IOU * BB)      // 1024 blocks in k_iou

// Persistent scratch (no cudaMalloc). Static zero-init; every kernel that
// consumes a value resets it for the next graph replay.
__device__ unsigned int g_mask[BB * CELLS / 4];   // 1 byte/cell, word access
__device__ unsigned int g_inter[BB];
__device__ unsigned int g_union[BB];
__device__ unsigned int g_ticket;

// ---------------------------------------------------------------------------
// K1: rasterize boxes into the byte mask. One CTA per (b, t) box.
// Mask is guaranteed clean: k_iou zeroes every word it reads.
// ---------------------------------------------------------------------------
__global__ void __launch_bounds__(128)
k_rasterize(const float* __restrict__ boxes) {
    const int bt = blockIdx.x;            // 0 .. B*T-1
    const int b  = bt / TT;
    const float* bx = boxes + (size_t)bt * 7;

    const float cx = bx[0], cy = bx[1], cz = bx[2];
    const float dx = bx[3], dy = bx[4], dz = bx[5], yaw = bx[6];

    // z test constant per box: |0.8 - cz| <= dz/2 (reference uses <=)
    if (fabsf(VOX - cz) > 0.5f * dz) return;

    const float c  = cosf(yaw), s = sinf(yaw);
    const float hx = 0.5f * dx, hy = 0.5f * dy;

    // rotated-box AABB (meters), +1 cell safety margin
    const float ax = hx * fabsf(c) + hy * fabsf(s);
    const float ay = hx * fabsf(s) + hy * fabsf(c);
    const int i0 = max(0,      (int)floorf((cx - ax) * INVVOX) - 1);
    const int i1 = min(HH - 1, (int)ceilf ((cx + ax) * INVVOX) + 1);
    const int j0 = max(0,      (int)floorf((cy - ay) * INVVOX) - 1);
    const int j1 = min(HH - 1, (int)ceilf ((cy + ay) * INVVOX) + 1);
    const int ni = i1 - i0 + 1, nj = j1 - j0 + 1;
    const int n  = ni * nj;

    unsigned char* mask = (unsigned char*)g_mask + (size_t)b * CELLS;

    for (int k = threadIdx.x; k < n; k += blockDim.x) {
        const int i = i0 + k / nj;
        const int j = j0 + k % nj;
        const float px = (float)i * VOX - cx;
        const float py = (float)j * VOX - cy;
        const float rx = fmaf(py, s,  px * c);      //  px*c + py*s
        const float ry = fmaf(py, c, -px * s);      // -px*s + py*c
        if (fabsf(rx) < hx && fabsf(ry) < hy)
            mask[i * HH + j] = 1;                    // idempotent; races benign
    }
}

// ---------------------------------------------------------------------------
// K2: masked channel-OR + IoU accumulate + self-clean mask + finalize.
// grid = (64, B), block = 256; each thread owns 4 consecutive cells.
// Identical load structure to the round-1 k_iou (measured ~8us).
// ---------------------------------------------------------------------------
__global__ void k_iou(const float* __restrict__ added,
                      const float* __restrict__ orig,
                      float* __restrict__ out) {
    const int b    = blockIdx.y;
    const int tid4 = blockIdx.x * blockDim.x + threadIdx.x;   // 0..16383
    const int cell0 = tid4 * 4;

    const int midx = b * (CELLS / 4) + tid4;
    const unsigned int mword = g_mask[midx];
    g_mask[midx] = 0u;                    // self-clean for next replay

    unsigned int inter = 0u, uni = 0u;

    if (mword != 0u) {
        const uint4* ap = (const uint4*)added + ((size_t)b * CC)         * (CELLS/4) + tid4;
        const uint4* op = (const uint4*)orig  + ((size_t)b * (CC+1) + 1) * (CELLS/4) + tid4;
        uint4 aa = make_uint4(0u,0u,0u,0u);
        uint4 ao = make_uint4(0u,0u,0u,0u);
        #pragma unroll 8
        for (int ch = 0; ch < CC; ch++) {
            const uint4 va = ap[(size_t)ch * (CELLS/4)];
            const uint4 vo = op[(size_t)ch * (CELLS/4)];
            aa.x |= va.x; aa.y |= va.y; aa.z |= va.z; aa.w |= va.w;
            ao.x |= vo.x; ao.y |= vo.y; ao.z |= vo.z; ao.w |= vo.w;
        }
        const unsigned int av[4] = {aa.x, aa.y, aa.z, aa.w};
        const unsigned int ov[4] = {ao.x, ao.y, ao.z, ao.w};
        #pragma unroll
        for (int k = 0; k < 4; k++) {
            const bool m = ((mword >> (8 * k)) & 0xFFu) != 0u;
            const bool p = m && (av[k] != 0u);   // sum!=0 <=> any bit set (nonneg)
            const bool o = m && (ov[k] != 0u);
            inter += (unsigned)(p && o);
            uni   += (unsigned)(p || o);
        }
    }

    // ---- block reduce ------------------------------------------------------
    inter = __reduce_add_sync(0xFFFFFFFFu, inter);
    uni   = __reduce_add_sync(0xFFFFFFFFu, uni);

    __shared__ unsigned int s_ri[8], s_ru[8];
    const int lane = threadIdx.x & 31;
    const int wid  = threadIdx.x >> 5;
    if (lane == 0) { s_ri[wid] = inter; s_ru[wid] = uni; }
    __syncthreads();
    if (wid == 0) {
        unsigned int vi = (lane < 8) ? s_ri[lane] : 0u;
        unsigned int vu = (lane < 8) ? s_ru[lane] : 0u;
        vi = __reduce_add_sync(0xFFFFFFFFu, vi);
        vu = __reduce_add_sync(0xFFFFFFFFu, vu);
        if (lane == 0 && (vi | vu)) {
            atomicAdd(&g_inter[b], vi);
            atomicAdd(&g_union[b], vu);
        }
    }

    // ---- last-block finalization (+ counter reset for next replay) --------
    __shared__ unsigned int s_last;
    if (threadIdx.x == 0) {
        __threadfence();
        s_last = (atomicAdd(&g_ticket, 1u) == (unsigned)(NBLOCKS - 1)) ? 1u : 0u;
    }
    __syncthreads();
    if (s_last && wid == 0) {
        float iou = 0.0f;
        if (lane < BB) {
            const unsigned int ai = g_inter[lane];
            const unsigned int au = g_union[lane];
            g_inter[lane] = 0u;                   // reset for next replay
            g_union[lane] = 0u;
            iou = (float)ai / fmaxf((float)au, 1.0f);
        }
        #pragma unroll
        for (int off = 16; off > 0; off >>= 1)
            iou += __shfl_xor_sync(0xFFFFFFFFu, iou, off);
        if (lane == 0) {
            out[0] = (float)TT * iou / (float)BB;
            __threadfence();
            g_ticket = 0u;                        // reset ticket
        }
    }
}

// ---------------------------------------------------------------------------
extern "C" void kernel_launch(void* const* d_in, const int* in_sizes, int n_in,
                              void* d_out, int out_size) {
    const float* added = (const float*)d_in[0];   // (16,32,256,256)
    const float* orig  = (const float*)d_in[1];   // (16,33,256,256)
    const float* boxes = (const float*)d_in[2];   // (16,20,7)
    (void)in_sizes; (void)n_in; (void)out_size;   // tf_ego unused

    k_rasterize<<<BB * TT, 128>>>(boxes);
    k_iou<<<dim3(GX_IOU, BB), 256>>>(added, orig, (float*)d_out);
}